// round 9
// baseline (speedup 1.0000x reference)
#include <cuda_runtime.h>
#include <cuda_bf16.h>

// Problem constants
#define BB 8
#define NPTS 16384
#define NG 512          // NUM_GROUPS
#define GS 32           // GROUP_SIZE
#define UK 512          // UPSCALE_K
#define CTX 256         // CONTEXT
#define R2 0.25f        // RADIUS^2

// Output layout (float32, flattened concat of the reference tuple)
#define OFF_GROUPS   0          // 8*256*32*4 = 262144
#define OFF_CENTERS  262144     // 8*256*4   = 8192
#define OFF_EMASK    270336     // 8*256     = 2048
#define OFF_PMASK    272384     // 8*256*32  = 65536

// ---------------- device scratch (no allocations allowed) ----------------
__device__ float4             g_centers[BB * NG];
__device__ float4             g_pcent[BB * NG];                   // progressive centers {x,y,z,idx}
__device__ unsigned           g_prog[BB];                         // published-center count
__device__ unsigned long long g_cand[(size_t)BB * NG * UK];       // 16MB candidate keys
__device__ int                g_cand_cnt[BB * NG];
__device__ int                g_group_len[BB];

// exact (no fma contraction) squared distance, reduce order ((dx^2+dy^2)+dz^2)
__device__ __forceinline__ float d2_exact(float dx, float dy, float dz) {
    return __fadd_rn(__fadd_rn(__fmul_rn(dx, dx), __fmul_rn(dy, dy)), __fmul_rn(dz, dz));
}

__device__ __forceinline__ unsigned encf(float f) {       // order-preserving float->u32
    unsigned u = __float_as_uint(f);
    return (u & 0x80000000u) ? ~u : (u | 0x80000000u);
}
__device__ __forceinline__ unsigned redux_max_u32(unsigned v) {
    unsigned r; asm("redux.sync.max.u32 %0, %1, 0xffffffff;" : "=r"(r) : "r"(v)); return r;
}
__device__ __forceinline__ unsigned redux_min_u32(unsigned v) {
    unsigned r; asm("redux.sync.min.u32 %0, %1, 0xffffffff;" : "=r"(r) : "r"(v)); return r;
}

// packed f32x2 helpers (two independent fp32 RN lanes — bit-exact vs scalar).
// NOTE (R8 post-mortem): only add/mul/fma exist in f32x2 form on sm_103a;
// min/max must stay scalar.
#define PACK2(o, lo, hi)  asm("mov.b64 %0, {%1, %2};" : "=l"(o) : "f"(lo), "f"(hi))
#define UNPACK2(lo, hi, i) asm("mov.b64 {%0, %1}, %2;" : "=f"(lo), "=f"(hi) : "l"(i))
#define ADDX2(o, a, b)    asm("add.rn.f32x2 %0, %1, %2;" : "=l"(o) : "l"(a), "l"(b))
#define MULX2(o, a, b)    asm("mul.rn.f32x2 %0, %1, %2;" : "=l"(o) : "l"(a), "l"(b))

// =====================================================================
// shims: keep ncu's capture point (4th launch) on the fused kernel;
// reset kernel zeroes the progress counters before every replay.
// =====================================================================
__global__ void nop_kernel() {}
__global__ void reset_kernel() { if (threadIdx.x < BB) g_prog[threadIdx.x] = 0; }

// =====================================================================
// FUSED kernel. CTAs 0..7: dense FPS (R7-proven core: packed add/mul d^2,
// scalar min/max bookkeeping, single barrier/iter, winner in registers in
// every warp). Each new center published progressively (STG + st.release).
// CTAs 8..135: ball-query consumers — warp owns 2 centers, polls progress
// with ld.acquire + nanosleep, scans as soon as its center exists.
// 136 CTAs <= 148 SMs -> all resident in wave 1 (no deadlock).
// =====================================================================
#define FPS_T 512
#define PAIRS 16
#define FPS_SMEM (NPTS * 8 + NPTS * 4)   // sxy[NPTS] float2 + z pairs float2[NPTS/2]

__global__ void __launch_bounds__(512, 1)
fused_kernel(const float4* __restrict__ pts, const int* __restrict__ lengths,
             float* __restrict__ out_centers /* d_out + OFF_CENTERS */) {
    const int wid = threadIdx.x >> 5, lane = threadIdx.x & 31;

    if (blockIdx.x < BB) {
        // ---------------- FPS role ----------------
        extern __shared__ float smem[];
        float2* __restrict__ sxy = (float2*)smem;              // [NPTS] by point
        float2* __restrict__ szp = (float2*)(smem + 2 * NPTS); // [NPTS/2] z pairs
        __shared__ unsigned long long s_wk[2][16];             // double-buffered warp keys
        __shared__ int s_cidx[NG];

        const int b = blockIdx.x, t = threadIdx.x;
        const float4* __restrict__ P = pts + (size_t)b * NPTS;
        const int len = lengths[b];

        unsigned long long X[PAIRS], Y[PAIRS];
        float mind[2 * PAIRS];

#pragma unroll
        for (int i = 0; i < PAIRS; i++) {
            int q = i * FPS_T + t;
            int p0 = 2 * q, p1 = 2 * q + 1;
            float4 v0 = P[p0], v1 = P[p1];
            bool va = (p0 < len), vb = (p1 < len);
            float x0 = va ? v0.x : 1e18f, y0 = va ? v0.y : 1e18f, z0 = va ? v0.z : 1e18f;
            float x1 = vb ? v1.x : 1e18f, y1 = vb ? v1.y : 1e18f, z1 = vb ? v1.z : 1e18f;
            PACK2(X[i], x0, x1);
            PACK2(Y[i], y0, y1);
            sxy[p0] = make_float2(x0, y0);
            sxy[p1] = make_float2(x1, y1);
            szp[q]  = make_float2(z0, z1);
            mind[2 * i]     = va ? 1e10f : -1e30f;
            mind[2 * i + 1] = vb ? 1e10f : -1e30f;
        }
        float4 v0 = __ldg(&P[0]);
        float wx = v0.x, wy = v0.y, wz = v0.z;
        int wpt = 0;
        if (t == 0) { s_cidx[0] = 0; g_group_len[b] = 0; }
        __syncthreads();

        for (int k = 1; k < NG; k++) {
            // publish center k-1 (fire-and-forget; drains under update shadow)
            if (t == 33) {
                float4 c = make_float4(wx, wy, wz, __int_as_float(wpt));
                *(float4*)&g_pcent[b * NG + (k - 1)] = c;
                asm volatile("st.release.gpu.global.b32 [%0], %1;"
                             :: "l"(&g_prog[b]), "r"((unsigned)k) : "memory");
            }
            unsigned long long nCx, nCy, nCz;
            PACK2(nCx, -wx, -wx);
            PACK2(nCy, -wy, -wy);
            PACK2(nCz, -wz, -wz);

            float fm = -1e30f;
#pragma unroll
            for (int i = 0; i < PAIRS; i++) {
                int q = i * FPS_T + t;
                float2 zz = szp[q];
                unsigned long long Zp, dx, dy, dz, sx, sy, sz, s1, d2p;
                PACK2(Zp, zz.x, zz.y);
                ADDX2(dx, X[i], nCx);           // x - cx  (add of negated, IEEE exact)
                ADDX2(dy, Y[i], nCy);
                ADDX2(dz, Zp,  nCz);
                MULX2(sx, dx, dx);
                MULX2(sy, dy, dy);
                MULX2(sz, dz, dz);
                ADDX2(s1, sx, sy);              // (dx^2 + dy^2)
                ADDX2(d2p, s1, sz);             // ... + dz^2   (same order as scalar)
                float lo, hi;
                UNPACK2(lo, hi, d2p);
                float m0 = fminf(mind[2 * i],     lo);
                float m1 = fminf(mind[2 * i + 1], hi);
                mind[2 * i] = m0; mind[2 * i + 1] = m1;
                fm = fmaxf(fm, fmaxf(m0, m1));
            }

            // warp argmax: max value (redux), min point index among matches
            unsigned ek = encf(fm);
            unsigned wm = redux_max_u32(ek);
            unsigned mybp = 0xFFFFFFFFu;
            if (ek == wm) {                      // predicated rescan (winning lanes only)
#pragma unroll
                for (int i = PAIRS - 1; i >= 0; i--) {
                    int q = i * FPS_T + t;
                    if (mind[2 * i + 1] == fm) mybp = (unsigned)(2 * q + 1);
                    if (mind[2 * i]     == fm) mybp = (unsigned)(2 * q);
                }
            }
            unsigned wi = redux_min_u32(mybp);
            const int par = k & 1;
            if (lane == 0)
                s_wk[par][wid] = ((unsigned long long)wm << 32) | (0xFFFFFFFFu - wi);
            __syncthreads();                     // ONE barrier per iteration

            // every warp redundantly reduces the 16 keys -> identical winner
            unsigned long long kk = (lane < 16) ? s_wk[par][lane] : 0ull;
            unsigned khi = (unsigned)(kk >> 32), klo = (unsigned)kk;
            unsigned mh = redux_max_u32(khi);
            unsigned ml = redux_max_u32((khi == mh) ? klo : 0u);
            wpt = (int)(0xFFFFFFFFu - ml);
            float2 xy = sxy[wpt];
            float2 z2 = szp[wpt >> 1];
            wx = xy.x; wy = xy.y; wz = (wpt & 1) ? z2.y : z2.x;
            if (t == 0) s_cidx[k] = wpt;
        }
        // publish final center
        if (t == 33) {
            float4 c = make_float4(wx, wy, wz, __int_as_float(wpt));
            *(float4*)&g_pcent[b * NG + (NG - 1)] = c;
            asm volatile("st.release.gpu.global.b32 [%0], %1;"
                         :: "l"(&g_prog[b]), "r"((unsigned)NG) : "memory");
        }
        __syncthreads();

        // tail: gather centers (all 4 channels incl. energy)
        {
            int p = s_cidx[threadIdx.x];
            float4 v = __ldg(&P[p]);
            g_centers[b * NG + threadIdx.x] = v;
            if (threadIdx.x < CTX) ((float4*)out_centers)[b * CTX + threadIdx.x] = v;
        }
    } else {
        // ---------------- ball-query consumer role ----------------
        const int cid = blockIdx.x - BB;
        const int W = cid * 16 + wid;            // 0..2047
        const int b = W >> 8;
        const int gi0 = W & 255;
        const int len = lengths[b];
        const float4* __restrict__ P = pts + (size_t)b * NPTS;
        const unsigned lt = (1u << lane) - 1u;
        const int lim = (len + 31) & ~31;

#pragma unroll
        for (int half = 0; half < 2; half++) {
            const int gi = gi0 + half * 256;
            float cx = 0.f, cy = 0.f, cz = 0.f;
            if (lane == 0) {
                unsigned need = (unsigned)(gi + 1);
                unsigned pr;
                while (true) {
                    asm volatile("ld.acquire.gpu.global.b32 %0, [%1];"
                                 : "=r"(pr) : "l"(&g_prog[b]) : "memory");
                    if (pr >= need) break;
                    __nanosleep(256);
                }
                float4 c = *(const float4*)&g_pcent[b * NG + gi];  // ordered after acquire
                cx = c.x; cy = c.y; cz = c.z;
            }
            cx = __shfl_sync(0xffffffffu, cx, 0);
            cy = __shfl_sync(0xffffffffu, cy, 0);
            cz = __shfl_sync(0xffffffffu, cz, 0);

            unsigned long long* __restrict__ buf = g_cand + (size_t)(b * NG + gi) * UK;
            int cnt = 0;
#pragma unroll 2
            for (int p0 = 0; p0 < lim; p0 += 32) {
                int p = p0 + lane;
                float4 v = __ldg(&P[p]);
                bool inlen = (p < len);
                float d2 = d2_exact(v.x - cx, v.y - cy, v.z - cz);
                bool pred = inlen && (d2 < R2);
                unsigned m = __ballot_sync(0xffffffffu, pred);
                if (m) {
                    int rnk = cnt + __popc(m & lt);
                    if (pred && rnk < UK) {
                        unsigned eb = __float_as_uint(v.w);
                        unsigned ekey = (eb & 0x80000000u) ? ~eb : (eb | 0x80000000u);
                        buf[rnk] = ((unsigned long long)ekey << 32)
                                 | (unsigned)(0xFFFFFFFFu - (unsigned)p);
                    }
                    cnt += __popc(m);
                    if (cnt >= UK) { cnt = UK; break; }
                }
            }
            if (lane == 0) g_cand_cnt[b * NG + gi] = cnt;
        }
    }
}

// =====================================================================
// K3: per-group adaptive bitonic (M = next pow2 >= cnt, min 32) descending
// sort of candidate keys, then emit. grid (512, 8), 256 threads.
// =====================================================================
__global__ __launch_bounds__(256, 8)
void sort_emit_kernel(const float4* __restrict__ pts,
                      float* __restrict__ out_groups /* d_out */,
                      float* __restrict__ out_pmask  /* d_out + OFF_PMASK */) {
    const int gi = blockIdx.x;
    const int b  = blockIdx.y;
    const int g  = b * NG + gi;
    const int t  = threadIdx.x;

    __shared__ unsigned long long s[UK];
    const int cnt = g_cand_cnt[g];
    const unsigned long long* __restrict__ src = g_cand + (size_t)g * UK;

    int M = GS;
    while (M < cnt) M <<= 1;                       // 32..512, CTA-uniform

    for (int i = t; i < M; i += 256)
        s[i] = (i < cnt) ? src[i] : 0ull;

    for (int kk = 2; kk <= M; kk <<= 1) {
        for (int j = kk >> 1; j > 0; j >>= 1) {
            __syncthreads();
            for (int e = t; e < M; e += 256) {
                int l = e ^ j;
                if (l > e) {
                    unsigned long long a = s[e], c = s[l];
                    bool dsc = ((e & kk) == 0);
                    bool sw = dsc ? (a < c) : (a > c);
                    if (sw) { s[e] = c; s[l] = a; }
                }
            }
        }
    }
    __syncthreads();

    const int pl = min(cnt, GS);
    if (t == 0 && cnt >= GS) atomicAdd(&g_group_len[b], 1);

    if (gi < CTX) {
        if (t < GS * 4) {
            int slot = t >> 2, ch = t & 3;
            int ss = (slot < pl) ? slot : 0;
            unsigned p = 0xFFFFFFFFu - (unsigned)(s[ss] & 0xFFFFFFFFull);
            const float* pp = (const float*)(pts + ((size_t)b * NPTS + p));
            out_groups[(((size_t)(b * CTX + gi)) * GS + slot) * 4 + ch] = pp[ch];
        } else if (t < GS * 4 + GS) {
            int slot = t - GS * 4;
            out_pmask[(size_t)(b * CTX + gi) * GS + slot] = (slot < pl) ? 1.0f : 0.0f;
        }
    }
}

// =====================================================================
// K4: embedding mask
// =====================================================================
__global__ void emask_kernel(float* __restrict__ em) {
    int b = blockIdx.x, t = threadIdx.x;
    em[b * CTX + t] = (t < g_group_len[b]) ? 1.0f : 0.0f;
}

// =====================================================================
extern "C" void kernel_launch(void* const* d_in, const int* in_sizes, int n_in,
                              void* d_out, int out_size) {
    const float4* pts = (const float4*)d_in[0];   // (8,16384,4) f32
    const int*   lens = (const int*)d_in[1];      // (8,)
    float* out = (float*)d_out;

    cudaFuncSetAttribute(fused_kernel,
                         cudaFuncAttributeMaxDynamicSharedMemorySize, FPS_SMEM);

    // 2 shims + reset so ncu's capture point (4th launch) = fused_kernel
    nop_kernel<<<1, 32>>>();
    nop_kernel<<<1, 32>>>();
    reset_kernel<<<1, 32>>>();
    fused_kernel<<<BB + 128, 512, FPS_SMEM>>>(pts, lens, out + OFF_CENTERS);
    sort_emit_kernel<<<dim3(NG, BB), 256>>>(pts, out + OFF_GROUPS, out + OFF_PMASK);
    emask_kernel<<<BB, CTX>>>(out + OFF_EMASK);
}

// round 10
// speedup vs baseline: 1.2828x; 1.2828x over previous
#include <cuda_runtime.h>
#include <cuda_bf16.h>

// Problem constants
#define BB 8
#define NPTS 16384
#define NG 512          // NUM_GROUPS
#define GS 32           // GROUP_SIZE
#define UK 512          // UPSCALE_K
#define CTX 256         // CONTEXT
#define R2 0.25f        // RADIUS^2

// Output layout (float32, flattened concat of the reference tuple)
#define OFF_GROUPS   0          // 8*256*32*4 = 262144
#define OFF_CENTERS  262144     // 8*256*4   = 8192
#define OFF_EMASK    270336     // 8*256     = 2048
#define OFF_PMASK    272384     // 8*256*32  = 65536

// ---------------- device scratch (no allocations allowed) ----------------
__device__ float4             g_centers[BB * NG];
__device__ unsigned long long g_cand[(size_t)BB * NG * UK];       // 16MB candidate keys
__device__ int                g_cand_cnt[BB * NG];
__device__ int                g_group_len[BB];

// exact (no fma contraction) squared distance, reduce order ((dx^2+dy^2)+dz^2)
__device__ __forceinline__ float d2_exact(float dx, float dy, float dz) {
    return __fadd_rn(__fadd_rn(__fmul_rn(dx, dx), __fmul_rn(dy, dy)), __fmul_rn(dz, dz));
}

__device__ __forceinline__ unsigned encf(float f) {       // order-preserving float->u32
    unsigned u = __float_as_uint(f);
    return (u & 0x80000000u) ? ~u : (u | 0x80000000u);
}
__device__ __forceinline__ unsigned redux_max_u32(unsigned v) {
    unsigned r; asm("redux.sync.max.u32 %0, %1, 0xffffffff;" : "=r"(r) : "r"(v)); return r;
}
__device__ __forceinline__ unsigned redux_min_u32(unsigned v) {
    unsigned r; asm("redux.sync.min.u32 %0, %1, 0xffffffff;" : "=r"(r) : "r"(v)); return r;
}

// packed f32x2 helpers (two independent fp32 RN lanes — bit-exact vs scalar).
// NOTE: only add/mul/fma exist in f32x2 form on sm_103a; min/max stay scalar.
#define PACK2(o, lo, hi)  asm("mov.b64 %0, {%1, %2};" : "=l"(o) : "f"(lo), "f"(hi))
#define UNPACK2(lo, hi, i) asm("mov.b64 {%0, %1}, %2;" : "=f"(lo), "=f"(hi) : "l"(i))
#define ADDX2(o, a, b)    asm("add.rn.f32x2 %0, %1, %2;" : "=l"(o) : "l"(a), "l"(b))
#define MULX2(o, a, b)    asm("mul.rn.f32x2 %0, %1, %2;" : "=l"(o) : "l"(a), "l"(b))

__global__ void nop_kernel() {}

// =====================================================================
// K1: dense FPS (R7-proven core). 1 CTA/batch, 512 threads, 16 pairs/thr.
// Packed add/mul d^2, scalar min/max, single barrier/iter, winner in
// registers in every warp via redundant redux reduce of 16 warp keys.
// =====================================================================
#define FPS_T 512
#define PAIRS 16
#define FPS_SMEM (NPTS * 8 + NPTS * 4)   // sxy[NPTS] float2 + z pairs float2[NPTS/2]

__global__ void __launch_bounds__(FPS_T, 1)
fps_kernel(const float4* __restrict__ pts, const int* __restrict__ lengths,
           float* __restrict__ out_centers /* d_out + OFF_CENTERS */) {
    extern __shared__ float smem[];
    float2* __restrict__ sxy = (float2*)smem;              // [NPTS] by point
    float2* __restrict__ szp = (float2*)(smem + 2 * NPTS); // [NPTS/2] z pairs
    __shared__ unsigned long long s_wk[2][16];             // double-buffered warp keys
    __shared__ int s_cidx[NG];

    const int b = blockIdx.x, t = threadIdx.x;
    const int wid = t >> 5, lane = t & 31;
    const float4* __restrict__ P = pts + (size_t)b * NPTS;
    const int len = lengths[b];

    unsigned long long X[PAIRS], Y[PAIRS];
    float mind[2 * PAIRS];

#pragma unroll
    for (int i = 0; i < PAIRS; i++) {
        int q = i * FPS_T + t;
        int p0 = 2 * q, p1 = 2 * q + 1;
        float4 v0 = P[p0], v1 = P[p1];
        bool va = (p0 < len), vb = (p1 < len);
        float x0 = va ? v0.x : 1e18f, y0 = va ? v0.y : 1e18f, z0 = va ? v0.z : 1e18f;
        float x1 = vb ? v1.x : 1e18f, y1 = vb ? v1.y : 1e18f, z1 = vb ? v1.z : 1e18f;
        PACK2(X[i], x0, x1);
        PACK2(Y[i], y0, y1);
        sxy[p0] = make_float2(x0, y0);
        sxy[p1] = make_float2(x1, y1);
        szp[q]  = make_float2(z0, z1);
        mind[2 * i]     = va ? 1e10f : -1e30f;
        mind[2 * i + 1] = vb ? 1e10f : -1e30f;
    }
    float4 v0 = __ldg(&P[0]);
    float wx = v0.x, wy = v0.y, wz = v0.z;
    int wpt = 0;
    if (t == 0) { s_cidx[0] = 0; g_group_len[b] = 0; }
    __syncthreads();

    for (int k = 1; k < NG; k++) {
        unsigned long long nCx, nCy, nCz;
        PACK2(nCx, -wx, -wx);
        PACK2(nCy, -wy, -wy);
        PACK2(nCz, -wz, -wz);

        float fm = -1e30f;
#pragma unroll
        for (int i = 0; i < PAIRS; i++) {
            int q = i * FPS_T + t;
            float2 zz = szp[q];
            unsigned long long Zp, dx, dy, dz, sx, sy, sz, s1, d2p;
            PACK2(Zp, zz.x, zz.y);
            ADDX2(dx, X[i], nCx);           // x - cx  (add of negated, IEEE exact)
            ADDX2(dy, Y[i], nCy);
            ADDX2(dz, Zp,  nCz);
            MULX2(sx, dx, dx);
            MULX2(sy, dy, dy);
            MULX2(sz, dz, dz);
            ADDX2(s1, sx, sy);              // (dx^2 + dy^2)
            ADDX2(d2p, s1, sz);             // ... + dz^2   (same order as scalar)
            float lo, hi;
            UNPACK2(lo, hi, d2p);
            float m0 = fminf(mind[2 * i],     lo);
            float m1 = fminf(mind[2 * i + 1], hi);
            mind[2 * i] = m0; mind[2 * i + 1] = m1;
            fm = fmaxf(fm, fmaxf(m0, m1));
        }

        // warp argmax: max value (redux), min point index among matches
        unsigned ek = encf(fm);
        unsigned wm = redux_max_u32(ek);
        unsigned mybp = 0xFFFFFFFFu;
        if (ek == wm) {                      // predicated rescan (winning lanes only)
#pragma unroll
            for (int i = PAIRS - 1; i >= 0; i--) {
                int q = i * FPS_T + t;
                if (mind[2 * i + 1] == fm) mybp = (unsigned)(2 * q + 1);
                if (mind[2 * i]     == fm) mybp = (unsigned)(2 * q);
            }
        }
        unsigned wi = redux_min_u32(mybp);
        const int par = k & 1;
        if (lane == 0)
            s_wk[par][wid] = ((unsigned long long)wm << 32) | (0xFFFFFFFFu - wi);
        __syncthreads();                     // ONE barrier per iteration

        // every warp redundantly reduces the 16 keys -> identical winner
        unsigned long long kk = (lane < 16) ? s_wk[par][lane] : 0ull;
        unsigned khi = (unsigned)(kk >> 32), klo = (unsigned)kk;
        unsigned mh = redux_max_u32(khi);
        unsigned ml = redux_max_u32((khi == mh) ? klo : 0u);
        wpt = (int)(0xFFFFFFFFu - ml);
        float2 xy = sxy[wpt];
        float2 z2 = szp[wpt >> 1];
        wx = xy.x; wy = xy.y; wz = (wpt & 1) ? z2.y : z2.x;
        if (t == 0) s_cidx[k] = wpt;
    }
    __syncthreads();

    // tail: gather centers (all 4 channels incl. energy)
    {
        int p = s_cidx[t];
        float4 v = __ldg(&P[p]);
        g_centers[b * NG + t] = v;
        if (t < CTX) ((float4*)out_centers)[b * CTX + t] = v;
    }
}

// =====================================================================
// K2: ball query, warp-per-center. grid (64, 8) = 512 CTAs, 256 threads
// (8 warps) -> ~7 warps/SMSP chip-wide: latency hidden, issue-bound.
// Fast path: tiles with ballot==0 (the common case at r=0.5) cost ~12
// instr. Ballot+popc rank preserves exact first-K-in-index-order; key
// packs (orderable energy << 32) | (0xFFFFFFFF - idx) as before.
// =====================================================================
__global__ __launch_bounds__(256, 4)
void ballquery_kernel(const float4* __restrict__ pts, const int* __restrict__ lengths) {
    const int b = blockIdx.y;
    const int wid = threadIdx.x >> 5, lane = threadIdx.x & 31;
    const int gi = blockIdx.x * 8 + wid;          // center index 0..511
    const int len = lengths[b];
    const float4* __restrict__ P = pts + (size_t)b * NPTS;
    const unsigned lt = (1u << lane) - 1u;
    const int lim = (len + 31) & ~31;

    float4 cc = g_centers[b * NG + gi];
    const float cx = cc.x, cy = cc.y, cz = cc.z;
    unsigned long long* __restrict__ buf = g_cand + (size_t)(b * NG + gi) * UK;

    int cnt = 0;
    for (int p0 = 0; p0 < lim; p0 += 32) {
        int p = p0 + lane;
        float4 v = __ldg(&P[p]);
        bool inlen = (p < len);
        float d2 = d2_exact(v.x - cx, v.y - cy, v.z - cz);
        bool pred = inlen && (d2 < R2);
        unsigned m = __ballot_sync(0xffffffffu, pred);
        if (m) {                                  // rare: tile has hits
            int rnk = cnt + __popc(m & lt);
            if (pred && rnk < UK) {
                unsigned eb = __float_as_uint(v.w);
                unsigned ekey = (eb & 0x80000000u) ? ~eb : (eb | 0x80000000u);
                buf[rnk] = ((unsigned long long)ekey << 32)
                         | (unsigned)(0xFFFFFFFFu - (unsigned)p);
            }
            cnt += __popc(m);
            if (cnt >= UK) { cnt = UK; break; }
        }
    }
    if (lane == 0) g_cand_cnt[b * NG + gi] = cnt;
}

// =====================================================================
// K3: per-group adaptive bitonic (M = next pow2 >= cnt, min 32) descending
// sort of candidate keys, then emit. grid (512, 8), 256 threads.
// =====================================================================
__global__ __launch_bounds__(256, 8)
void sort_emit_kernel(const float4* __restrict__ pts,
                      float* __restrict__ out_groups /* d_out */,
                      float* __restrict__ out_pmask  /* d_out + OFF_PMASK */) {
    const int gi = blockIdx.x;
    const int b  = blockIdx.y;
    const int g  = b * NG + gi;
    const int t  = threadIdx.x;

    __shared__ unsigned long long s[UK];
    const int cnt = g_cand_cnt[g];
    const unsigned long long* __restrict__ src = g_cand + (size_t)g * UK;

    int M = GS;
    while (M < cnt) M <<= 1;                       // 32..512, CTA-uniform

    for (int i = t; i < M; i += 256)
        s[i] = (i < cnt) ? src[i] : 0ull;

    for (int kk = 2; kk <= M; kk <<= 1) {
        for (int j = kk >> 1; j > 0; j >>= 1) {
            __syncthreads();
            for (int e = t; e < M; e += 256) {
                int l = e ^ j;
                if (l > e) {
                    unsigned long long a = s[e], c = s[l];
                    bool dsc = ((e & kk) == 0);
                    bool sw = dsc ? (a < c) : (a > c);
                    if (sw) { s[e] = c; s[l] = a; }
                }
            }
        }
    }
    __syncthreads();

    const int pl = min(cnt, GS);
    if (t == 0 && cnt >= GS) atomicAdd(&g_group_len[b], 1);

    if (gi < CTX) {
        if (t < GS * 4) {
            int slot = t >> 2, ch = t & 3;
            int ss = (slot < pl) ? slot : 0;
            unsigned p = 0xFFFFFFFFu - (unsigned)(s[ss] & 0xFFFFFFFFull);
            const float* pp = (const float*)(pts + ((size_t)b * NPTS + p));
            out_groups[(((size_t)(b * CTX + gi)) * GS + slot) * 4 + ch] = pp[ch];
        } else if (t < GS * 4 + GS) {
            int slot = t - GS * 4;
            out_pmask[(size_t)(b * CTX + gi) * GS + slot] = (slot < pl) ? 1.0f : 0.0f;
        }
    }
}

// =====================================================================
// K4: embedding mask
// =====================================================================
__global__ void emask_kernel(float* __restrict__ em) {
    int b = blockIdx.x, t = threadIdx.x;
    em[b * CTX + t] = (t < g_group_len[b]) ? 1.0f : 0.0f;
}

// =====================================================================
extern "C" void kernel_launch(void* const* d_in, const int* in_sizes, int n_in,
                              void* d_out, int out_size) {
    const float4* pts = (const float4*)d_in[0];   // (8,16384,4) f32
    const int*   lens = (const int*)d_in[1];      // (8,)
    float* out = (float*)d_out;

    cudaFuncSetAttribute(fps_kernel,
                         cudaFuncAttributeMaxDynamicSharedMemorySize, FPS_SMEM);

    // ballquery is launch #4 -> ncu capture lands on it this round
    fps_kernel<<<BB, FPS_T, FPS_SMEM>>>(pts, lens, out + OFF_CENTERS);
    nop_kernel<<<1, 32>>>();
    nop_kernel<<<1, 32>>>();
    ballquery_kernel<<<dim3(64, BB), 256>>>(pts, lens);
    sort_emit_kernel<<<dim3(NG, BB), 256>>>(pts, out + OFF_GROUPS, out + OFF_PMASK);
    emask_kernel<<<BB, CTX>>>(out + OFF_EMASK);
}

// round 11
// speedup vs baseline: 1.3546x; 1.0560x over previous
#include <cuda_runtime.h>
#include <cuda_bf16.h>

// Problem constants
#define BB 8
#define NPTS 16384
#define NG 512          // NUM_GROUPS
#define GS 32           // GROUP_SIZE
#define UK 512          // UPSCALE_K
#define CTX 256         // CONTEXT
#define R2 0.25f        // RADIUS^2

// Output layout (float32, flattened concat of the reference tuple)
#define OFF_GROUPS   0          // 8*256*32*4 = 262144
#define OFF_CENTERS  262144     // 8*256*4   = 8192
#define OFF_EMASK    270336     // 8*256     = 2048
#define OFF_PMASK    272384     // 8*256*32  = 65536

// ---------------- device scratch (no allocations allowed) ----------------
__device__ float4             g_centers[BB * NG];
__device__ unsigned long long g_cand[(size_t)BB * NG * UK];       // 16MB candidate keys
__device__ int                g_cand_cnt[BB * NG];
__device__ int                g_group_len[BB];

// exact (no fma contraction) squared distance, reduce order ((dx^2+dy^2)+dz^2)
__device__ __forceinline__ float d2_exact(float dx, float dy, float dz) {
    return __fadd_rn(__fadd_rn(__fmul_rn(dx, dx), __fmul_rn(dy, dy)), __fmul_rn(dz, dz));
}

__device__ __forceinline__ unsigned encf(float f) {       // order-preserving float->u32
    unsigned u = __float_as_uint(f);
    return (u & 0x80000000u) ? ~u : (u | 0x80000000u);
}
__device__ __forceinline__ unsigned redux_max_u32(unsigned v) {
    unsigned r; asm("redux.sync.max.u32 %0, %1, 0xffffffff;" : "=r"(r) : "r"(v)); return r;
}
__device__ __forceinline__ unsigned redux_min_u32(unsigned v) {
    unsigned r; asm("redux.sync.min.u32 %0, %1, 0xffffffff;" : "=r"(r) : "r"(v)); return r;
}

// packed f32x2 helpers (two independent fp32 RN lanes — bit-exact vs scalar).
// NOTE: only add/mul/fma exist in f32x2 form on sm_103a; min/max stay scalar.
#define PACK2(o, lo, hi)  asm("mov.b64 %0, {%1, %2};" : "=l"(o) : "f"(lo), "f"(hi))
#define UNPACK2(lo, hi, i) asm("mov.b64 {%0, %1}, %2;" : "=f"(lo), "=f"(hi) : "l"(i))
#define ADDX2(o, a, b)    asm("add.rn.f32x2 %0, %1, %2;" : "=l"(o) : "l"(a), "l"(b))
#define MULX2(o, a, b)    asm("mul.rn.f32x2 %0, %1, %2;" : "=l"(o) : "l"(a), "l"(b))

__global__ void nop_kernel() {}

// =====================================================================
// K1: dense FPS (R7-proven core). 1 CTA/batch, 512 threads, 16 pairs/thr.
// Packed add/mul d^2, scalar min/max, single barrier/iter, winner in
// registers in every warp via redundant redux reduce of 16 warp keys.
// =====================================================================
#define FPS_T 512
#define PAIRS 16
#define FPS_SMEM (NPTS * 8 + NPTS * 4)   // sxy[NPTS] float2 + z pairs float2[NPTS/2]

__global__ void __launch_bounds__(FPS_T, 1)
fps_kernel(const float4* __restrict__ pts, const int* __restrict__ lengths,
           float* __restrict__ out_centers /* d_out + OFF_CENTERS */) {
    extern __shared__ float smem[];
    float2* __restrict__ sxy = (float2*)smem;              // [NPTS] by point
    float2* __restrict__ szp = (float2*)(smem + 2 * NPTS); // [NPTS/2] z pairs
    __shared__ unsigned long long s_wk[2][16];             // double-buffered warp keys
    __shared__ int s_cidx[NG];

    const int b = blockIdx.x, t = threadIdx.x;
    const int wid = t >> 5, lane = t & 31;
    const float4* __restrict__ P = pts + (size_t)b * NPTS;
    const int len = lengths[b];

    unsigned long long X[PAIRS], Y[PAIRS];
    float mind[2 * PAIRS];

#pragma unroll
    for (int i = 0; i < PAIRS; i++) {
        int q = i * FPS_T + t;
        int p0 = 2 * q, p1 = 2 * q + 1;
        float4 v0 = P[p0], v1 = P[p1];
        bool va = (p0 < len), vb = (p1 < len);
        float x0 = va ? v0.x : 1e18f, y0 = va ? v0.y : 1e18f, z0 = va ? v0.z : 1e18f;
        float x1 = vb ? v1.x : 1e18f, y1 = vb ? v1.y : 1e18f, z1 = vb ? v1.z : 1e18f;
        PACK2(X[i], x0, x1);
        PACK2(Y[i], y0, y1);
        sxy[p0] = make_float2(x0, y0);
        sxy[p1] = make_float2(x1, y1);
        szp[q]  = make_float2(z0, z1);
        mind[2 * i]     = va ? 1e10f : -1e30f;
        mind[2 * i + 1] = vb ? 1e10f : -1e30f;
    }
    float4 v0 = __ldg(&P[0]);
    float wx = v0.x, wy = v0.y, wz = v0.z;
    int wpt = 0;
    if (t == 0) { s_cidx[0] = 0; g_group_len[b] = 0; }
    __syncthreads();

    for (int k = 1; k < NG; k++) {
        unsigned long long nCx, nCy, nCz;
        PACK2(nCx, -wx, -wx);
        PACK2(nCy, -wy, -wy);
        PACK2(nCz, -wz, -wz);

        float fm = -1e30f;
#pragma unroll
        for (int i = 0; i < PAIRS; i++) {
            int q = i * FPS_T + t;
            float2 zz = szp[q];
            unsigned long long Zp, dx, dy, dz, sx, sy, sz, s1, d2p;
            PACK2(Zp, zz.x, zz.y);
            ADDX2(dx, X[i], nCx);           // x - cx  (add of negated, IEEE exact)
            ADDX2(dy, Y[i], nCy);
            ADDX2(dz, Zp,  nCz);
            MULX2(sx, dx, dx);
            MULX2(sy, dy, dy);
            MULX2(sz, dz, dz);
            ADDX2(s1, sx, sy);              // (dx^2 + dy^2)
            ADDX2(d2p, s1, sz);             // ... + dz^2   (same order as scalar)
            float lo, hi;
            UNPACK2(lo, hi, d2p);
            float m0 = fminf(mind[2 * i],     lo);
            float m1 = fminf(mind[2 * i + 1], hi);
            mind[2 * i] = m0; mind[2 * i + 1] = m1;
            fm = fmaxf(fm, fmaxf(m0, m1));
        }

        // warp argmax: max value (redux), min point index among matches
        unsigned ek = encf(fm);
        unsigned wm = redux_max_u32(ek);
        unsigned mybp = 0xFFFFFFFFu;
        if (ek == wm) {                      // predicated rescan (winning lanes only)
#pragma unroll
            for (int i = PAIRS - 1; i >= 0; i--) {
                int q = i * FPS_T + t;
                if (mind[2 * i + 1] == fm) mybp = (unsigned)(2 * q + 1);
                if (mind[2 * i]     == fm) mybp = (unsigned)(2 * q);
            }
        }
        unsigned wi = redux_min_u32(mybp);
        const int par = k & 1;
        if (lane == 0)
            s_wk[par][wid] = ((unsigned long long)wm << 32) | (0xFFFFFFFFu - wi);
        __syncthreads();                     // ONE barrier per iteration

        // every warp redundantly reduces the 16 keys -> identical winner
        unsigned long long kk = (lane < 16) ? s_wk[par][lane] : 0ull;
        unsigned khi = (unsigned)(kk >> 32), klo = (unsigned)kk;
        unsigned mh = redux_max_u32(khi);
        unsigned ml = redux_max_u32((khi == mh) ? klo : 0u);
        wpt = (int)(0xFFFFFFFFu - ml);
        float2 xy = sxy[wpt];
        float2 z2 = szp[wpt >> 1];
        wx = xy.x; wy = xy.y; wz = (wpt & 1) ? z2.y : z2.x;
        if (t == 0) s_cidx[k] = wpt;
    }
    __syncthreads();

    // tail: gather centers (all 4 channels incl. energy)
    {
        int p = s_cidx[t];
        float4 v = __ldg(&P[p]);
        g_centers[b * NG + t] = v;
        if (t < CTX) ((float4*)out_centers)[b * CTX + t] = v;
    }
}

// =====================================================================
// K2: ball query, warp-per-center, MLP=4. grid (64, 8), 256 threads.
// 4 independent LDG.128 tiles are front-batched, then the 4 ballot
// rounds run in order — exposed gmem latency /4. Candidate set and
// order identical to the serial version (rank math unchanged).
// =====================================================================
__global__ __launch_bounds__(256, 4)
void ballquery_kernel(const float4* __restrict__ pts, const int* __restrict__ lengths) {
    const int b = blockIdx.y;
    const int wid = threadIdx.x >> 5, lane = threadIdx.x & 31;
    const int gi = blockIdx.x * 8 + wid;          // center index 0..511
    const int len = lengths[b];
    const float4* __restrict__ P = pts + (size_t)b * NPTS;
    const unsigned lt = (1u << lane) - 1u;

    float4 cc = g_centers[b * NG + gi];
    const float cx = cc.x, cy = cc.y, cz = cc.z;
    unsigned long long* __restrict__ buf = g_cand + (size_t)(b * NG + gi) * UK;

    int cnt = 0;
    for (int p0 = 0; p0 < NPTS && cnt < UK; p0 += 128) {
        float4 v[4];
#pragma unroll
        for (int j = 0; j < 4; j++)                // 4 independent loads: MLP=4
            v[j] = __ldg(&P[p0 + j * 32 + lane]);
#pragma unroll
        for (int j = 0; j < 4; j++) {              // ordered ballot rounds
            int p = p0 + j * 32 + lane;
            bool pred = (p < len) && (d2_exact(v[j].x - cx, v[j].y - cy, v[j].z - cz) < R2);
            unsigned m = __ballot_sync(0xffffffffu, pred);
            if (m) {
                int rnk = cnt + __popc(m & lt);
                if (pred && rnk < UK) {
                    unsigned eb = __float_as_uint(v[j].w);
                    unsigned ekey = (eb & 0x80000000u) ? ~eb : (eb | 0x80000000u);
                    buf[rnk] = ((unsigned long long)ekey << 32)
                             | (unsigned)(0xFFFFFFFFu - (unsigned)p);
                }
                cnt += __popc(m);
                if (cnt >= UK) { cnt = UK; break; }
            }
        }
    }
    if (lane == 0) g_cand_cnt[b * NG + gi] = cnt;
}

// =====================================================================
// K3: per-group adaptive bitonic (M = next pow2 >= cnt, min 32) descending
// sort of candidate keys, then emit. grid (512, 8), 256 threads.
// =====================================================================
__global__ __launch_bounds__(256, 8)
void sort_emit_kernel(const float4* __restrict__ pts,
                      float* __restrict__ out_groups /* d_out */,
                      float* __restrict__ out_pmask  /* d_out + OFF_PMASK */) {
    const int gi = blockIdx.x;
    const int b  = blockIdx.y;
    const int g  = b * NG + gi;
    const int t  = threadIdx.x;

    __shared__ unsigned long long s[UK];
    const int cnt = g_cand_cnt[g];
    const unsigned long long* __restrict__ src = g_cand + (size_t)g * UK;

    int M = GS;
    while (M < cnt) M <<= 1;                       // 32..512, CTA-uniform

    for (int i = t; i < M; i += 256)
        s[i] = (i < cnt) ? src[i] : 0ull;

    for (int kk = 2; kk <= M; kk <<= 1) {
        for (int j = kk >> 1; j > 0; j >>= 1) {
            __syncthreads();
            for (int e = t; e < M; e += 256) {
                int l = e ^ j;
                if (l > e) {
                    unsigned long long a = s[e], c = s[l];
                    bool dsc = ((e & kk) == 0);
                    bool sw = dsc ? (a < c) : (a > c);
                    if (sw) { s[e] = c; s[l] = a; }
                }
            }
        }
    }
    __syncthreads();

    const int pl = min(cnt, GS);
    if (t == 0 && cnt >= GS) atomicAdd(&g_group_len[b], 1);

    if (gi < CTX) {
        if (t < GS * 4) {
            int slot = t >> 2, ch = t & 3;
            int ss = (slot < pl) ? slot : 0;
            unsigned p = 0xFFFFFFFFu - (unsigned)(s[ss] & 0xFFFFFFFFull);
            const float* pp = (const float*)(pts + ((size_t)b * NPTS + p));
            out_groups[(((size_t)(b * CTX + gi)) * GS + slot) * 4 + ch] = pp[ch];
        } else if (t < GS * 4 + GS) {
            int slot = t - GS * 4;
            out_pmask[(size_t)(b * CTX + gi) * GS + slot] = (slot < pl) ? 1.0f : 0.0f;
        }
    }
}

// =====================================================================
// K4: embedding mask
// =====================================================================
__global__ void emask_kernel(float* __restrict__ em) {
    int b = blockIdx.x, t = threadIdx.x;
    em[b * CTX + t] = (t < g_group_len[b]) ? 1.0f : 0.0f;
}

// =====================================================================
extern "C" void kernel_launch(void* const* d_in, const int* in_sizes, int n_in,
                              void* d_out, int out_size) {
    const float4* pts = (const float4*)d_in[0];   // (8,16384,4) f32
    const int*   lens = (const int*)d_in[1];      // (8,)
    float* out = (float*)d_out;

    cudaFuncSetAttribute(fps_kernel,
                         cudaFuncAttributeMaxDynamicSharedMemorySize, FPS_SMEM);

    // ballquery stays launch #4 -> ncu capture verifies the MLP fix
    fps_kernel<<<BB, FPS_T, FPS_SMEM>>>(pts, lens, out + OFF_CENTERS);
    nop_kernel<<<1, 32>>>();
    nop_kernel<<<1, 32>>>();
    ballquery_kernel<<<dim3(64, BB), 256>>>(pts, lens);
    sort_emit_kernel<<<dim3(NG, BB), 256>>>(pts, out + OFF_GROUPS, out + OFF_PMASK);
    emask_kernel<<<BB, CTX>>>(out + OFF_EMASK);
}

// round 12
// speedup vs baseline: 1.3684x; 1.0102x over previous
#include <cuda_runtime.h>
#include <cuda_bf16.h>

// Problem constants
#define BB 8
#define NPTS 16384
#define NG 512          // NUM_GROUPS
#define GS 32           // GROUP_SIZE
#define UK 512          // UPSCALE_K
#define CTX 256         // CONTEXT
#define R2 0.25f        // RADIUS^2

// Output layout (float32, flattened concat of the reference tuple)
#define OFF_GROUPS   0          // 8*256*32*4 = 262144
#define OFF_CENTERS  262144     // 8*256*4   = 8192
#define OFF_EMASK    270336     // 8*256     = 2048
#define OFF_PMASK    272384     // 8*256*32  = 65536

// ---------------- device scratch (no allocations allowed) ----------------
__device__ float4             g_centers[BB * NG];
__device__ unsigned long long g_cand[(size_t)BB * NG * UK];       // 16MB candidate keys
__device__ int                g_cand_cnt[BB * NG];
__device__ int                g_group_len[BB];

// exact (no fma contraction) squared distance, reduce order ((dx^2+dy^2)+dz^2)
__device__ __forceinline__ float d2_exact(float dx, float dy, float dz) {
    return __fadd_rn(__fadd_rn(__fmul_rn(dx, dx), __fmul_rn(dy, dy)), __fmul_rn(dz, dz));
}

__device__ __forceinline__ unsigned encf(float f) {       // order-preserving float->u32
    unsigned u = __float_as_uint(f);
    return (u & 0x80000000u) ? ~u : (u | 0x80000000u);
}
__device__ __forceinline__ unsigned redux_max_u32(unsigned v) {
    unsigned r; asm("redux.sync.max.u32 %0, %1, 0xffffffff;" : "=r"(r) : "r"(v)); return r;
}
__device__ __forceinline__ unsigned redux_min_u32(unsigned v) {
    unsigned r; asm("redux.sync.min.u32 %0, %1, 0xffffffff;" : "=r"(r) : "r"(v)); return r;
}

// packed f32x2 helpers (two independent fp32 RN lanes — bit-exact vs scalar).
// NOTE: only add/mul/fma exist in f32x2 form on sm_103a; min/max stay scalar.
#define PACK2(o, lo, hi)  asm("mov.b64 %0, {%1, %2};" : "=l"(o) : "f"(lo), "f"(hi))
#define UNPACK2(lo, hi, i) asm("mov.b64 {%0, %1}, %2;" : "=f"(lo), "=f"(hi) : "l"(i))
#define ADDX2(o, a, b)    asm("add.rn.f32x2 %0, %1, %2;" : "=l"(o) : "l"(a), "l"(b))
#define MULX2(o, a, b)    asm("mul.rn.f32x2 %0, %1, %2;" : "=l"(o) : "l"(a), "l"(b))

__global__ void nop_kernel() {}

// =====================================================================
// K1: dense FPS, 1024 threads (8 warps/SMSP for latency hiding),
// 8 point-pairs/thread. X,Y packed in registers (32 regs), mind[16],
// z pairs in smem. Same single-barrier iteration and redundant
// 32-key redux reduce; arithmetic bit-identical to the 512-thr version.
// =====================================================================
#define FPS_T 1024
#define PAIRS 8
#define FPS_SMEM (NPTS * 8 + NPTS * 4)   // sxy[NPTS] float2 + z pairs float2[NPTS/2]

__global__ void __launch_bounds__(FPS_T, 1)
fps_kernel(const float4* __restrict__ pts, const int* __restrict__ lengths,
           float* __restrict__ out_centers /* d_out + OFF_CENTERS */) {
    extern __shared__ float smem[];
    float2* __restrict__ sxy = (float2*)smem;              // [NPTS] by point
    float2* __restrict__ szp = (float2*)(smem + 2 * NPTS); // [NPTS/2] z pairs
    __shared__ unsigned long long s_wk[2][32];             // double-buffered warp keys
    __shared__ int s_cidx[NG];

    const int b = blockIdx.x, t = threadIdx.x;
    const int wid = t >> 5, lane = t & 31;
    const float4* __restrict__ P = pts + (size_t)b * NPTS;
    const int len = lengths[b];

    unsigned long long X[PAIRS], Y[PAIRS];
    float mind[2 * PAIRS];

#pragma unroll
    for (int i = 0; i < PAIRS; i++) {
        int q = i * FPS_T + t;
        int p0 = 2 * q, p1 = 2 * q + 1;
        float4 v0 = P[p0], v1 = P[p1];
        bool va = (p0 < len), vb = (p1 < len);
        float x0 = va ? v0.x : 1e18f, y0 = va ? v0.y : 1e18f, z0 = va ? v0.z : 1e18f;
        float x1 = vb ? v1.x : 1e18f, y1 = vb ? v1.y : 1e18f, z1 = vb ? v1.z : 1e18f;
        PACK2(X[i], x0, x1);
        PACK2(Y[i], y0, y1);
        sxy[p0] = make_float2(x0, y0);
        sxy[p1] = make_float2(x1, y1);
        szp[q]  = make_float2(z0, z1);
        mind[2 * i]     = va ? 1e10f : -1e30f;
        mind[2 * i + 1] = vb ? 1e10f : -1e30f;
    }
    float4 v0 = __ldg(&P[0]);
    float wx = v0.x, wy = v0.y, wz = v0.z;
    int wpt = 0;
    if (t == 0) { s_cidx[0] = 0; g_group_len[b] = 0; }
    __syncthreads();

    for (int k = 1; k < NG; k++) {
        unsigned long long nCx, nCy, nCz;
        PACK2(nCx, -wx, -wx);
        PACK2(nCy, -wy, -wy);
        PACK2(nCz, -wz, -wz);

        float fm = -1e30f;
#pragma unroll
        for (int i = 0; i < PAIRS; i++) {
            int q = i * FPS_T + t;
            float2 zz = szp[q];
            unsigned long long Zp, dx, dy, dz, sx, sy, sz, s1, d2p;
            PACK2(Zp, zz.x, zz.y);
            ADDX2(dx, X[i], nCx);           // x - cx  (add of negated, IEEE exact)
            ADDX2(dy, Y[i], nCy);
            ADDX2(dz, Zp,  nCz);
            MULX2(sx, dx, dx);
            MULX2(sy, dy, dy);
            MULX2(sz, dz, dz);
            ADDX2(s1, sx, sy);              // (dx^2 + dy^2)
            ADDX2(d2p, s1, sz);             // ... + dz^2   (same order as scalar)
            float lo, hi;
            UNPACK2(lo, hi, d2p);
            float m0 = fminf(mind[2 * i],     lo);
            float m1 = fminf(mind[2 * i + 1], hi);
            mind[2 * i] = m0; mind[2 * i + 1] = m1;
            fm = fmaxf(fm, fmaxf(m0, m1));
        }

        // warp argmax: max value (redux), min point index among matches
        unsigned ek = encf(fm);
        unsigned wm = redux_max_u32(ek);
        unsigned mybp = 0xFFFFFFFFu;
        if (ek == wm) {                      // predicated rescan (winning lanes only)
#pragma unroll
            for (int i = PAIRS - 1; i >= 0; i--) {
                int q = i * FPS_T + t;
                if (mind[2 * i + 1] == fm) mybp = (unsigned)(2 * q + 1);
                if (mind[2 * i]     == fm) mybp = (unsigned)(2 * q);
            }
        }
        unsigned wi = redux_min_u32(mybp);
        const int par = k & 1;
        if (lane == 0)
            s_wk[par][wid] = ((unsigned long long)wm << 32) | (0xFFFFFFFFu - wi);
        __syncthreads();                     // ONE barrier per iteration

        // every warp redundantly reduces the 32 keys -> identical winner
        unsigned long long kk = s_wk[par][lane];
        unsigned khi = (unsigned)(kk >> 32), klo = (unsigned)kk;
        unsigned mh = redux_max_u32(khi);
        unsigned ml = redux_max_u32((khi == mh) ? klo : 0u);
        wpt = (int)(0xFFFFFFFFu - ml);
        float2 xy = sxy[wpt];
        float2 z2 = szp[wpt >> 1];
        wx = xy.x; wy = xy.y; wz = (wpt & 1) ? z2.y : z2.x;
        if (t == 0) s_cidx[k] = wpt;
    }
    __syncthreads();

    // tail: gather centers (all 4 channels incl. energy)
    if (t < NG) {
        int p = s_cidx[t];
        float4 v = __ldg(&P[p]);
        g_centers[b * NG + t] = v;
        if (t < CTX) ((float4*)out_centers)[b * CTX + t] = v;
    }
}

// =====================================================================
// K2: ball query, warp-per-center, MLP=8. grid (64, 8), 256 threads.
// 8 independent LDG.128 tiles front-batched, then 8 ordered ballot
// rounds — exposed gmem latency /8. Candidate set/order unchanged.
// =====================================================================
__global__ __launch_bounds__(256, 4)
void ballquery_kernel(const float4* __restrict__ pts, const int* __restrict__ lengths) {
    const int b = blockIdx.y;
    const int wid = threadIdx.x >> 5, lane = threadIdx.x & 31;
    const int gi = blockIdx.x * 8 + wid;          // center index 0..511
    const int len = lengths[b];
    const float4* __restrict__ P = pts + (size_t)b * NPTS;
    const unsigned lt = (1u << lane) - 1u;

    float4 cc = g_centers[b * NG + gi];
    const float cx = cc.x, cy = cc.y, cz = cc.z;
    unsigned long long* __restrict__ buf = g_cand + (size_t)(b * NG + gi) * UK;

    int cnt = 0;
    for (int p0 = 0; p0 < NPTS && cnt < UK; p0 += 256) {
        float4 v[8];
#pragma unroll
        for (int j = 0; j < 8; j++)                // 8 independent loads: MLP=8
            v[j] = __ldg(&P[p0 + j * 32 + lane]);
#pragma unroll
        for (int j = 0; j < 8; j++) {              // ordered ballot rounds
            int p = p0 + j * 32 + lane;
            bool pred = (p < len) && (d2_exact(v[j].x - cx, v[j].y - cy, v[j].z - cz) < R2);
            unsigned m = __ballot_sync(0xffffffffu, pred);
            if (m) {
                int rnk = cnt + __popc(m & lt);
                if (pred && rnk < UK) {
                    unsigned eb = __float_as_uint(v[j].w);
                    unsigned ekey = (eb & 0x80000000u) ? ~eb : (eb | 0x80000000u);
                    buf[rnk] = ((unsigned long long)ekey << 32)
                             | (unsigned)(0xFFFFFFFFu - (unsigned)p);
                }
                cnt += __popc(m);
                if (cnt >= UK) { cnt = UK; break; }
            }
        }
    }
    if (lane == 0) g_cand_cnt[b * NG + gi] = cnt;
}

// =====================================================================
// K3: per-group adaptive bitonic (M = next pow2 >= cnt, min 32) descending
// sort of candidate keys, then emit. grid (512, 8), 256 threads.
// =====================================================================
__global__ __launch_bounds__(256, 8)
void sort_emit_kernel(const float4* __restrict__ pts,
                      float* __restrict__ out_groups /* d_out */,
                      float* __restrict__ out_pmask  /* d_out + OFF_PMASK */) {
    const int gi = blockIdx.x;
    const int b  = blockIdx.y;
    const int g  = b * NG + gi;
    const int t  = threadIdx.x;

    __shared__ unsigned long long s[UK];
    const int cnt = g_cand_cnt[g];
    const unsigned long long* __restrict__ src = g_cand + (size_t)g * UK;

    int M = GS;
    while (M < cnt) M <<= 1;                       // 32..512, CTA-uniform

    for (int i = t; i < M; i += 256)
        s[i] = (i < cnt) ? src[i] : 0ull;

    for (int kk = 2; kk <= M; kk <<= 1) {
        for (int j = kk >> 1; j > 0; j >>= 1) {
            __syncthreads();
            for (int e = t; e < M; e += 256) {
                int l = e ^ j;
                if (l > e) {
                    unsigned long long a = s[e], c = s[l];
                    bool dsc = ((e & kk) == 0);
                    bool sw = dsc ? (a < c) : (a > c);
                    if (sw) { s[e] = c; s[l] = a; }
                }
            }
        }
    }
    __syncthreads();

    const int pl = min(cnt, GS);
    if (t == 0 && cnt >= GS) atomicAdd(&g_group_len[b], 1);

    if (gi < CTX) {
        if (t < GS * 4) {
            int slot = t >> 2, ch = t & 3;
            int ss = (slot < pl) ? slot : 0;
            unsigned p = 0xFFFFFFFFu - (unsigned)(s[ss] & 0xFFFFFFFFull);
            const float* pp = (const float*)(pts + ((size_t)b * NPTS + p));
            out_groups[(((size_t)(b * CTX + gi)) * GS + slot) * 4 + ch] = pp[ch];
        } else if (t < GS * 4 + GS) {
            int slot = t - GS * 4;
            out_pmask[(size_t)(b * CTX + gi) * GS + slot] = (slot < pl) ? 1.0f : 0.0f;
        }
    }
}

// =====================================================================
// K4: embedding mask
// =====================================================================
__global__ void emask_kernel(float* __restrict__ em) {
    int b = blockIdx.x, t = threadIdx.x;
    em[b * CTX + t] = (t < g_group_len[b]) ? 1.0f : 0.0f;
}

// =====================================================================
extern "C" void kernel_launch(void* const* d_in, const int* in_sizes, int n_in,
                              void* d_out, int out_size) {
    const float4* pts = (const float4*)d_in[0];   // (8,16384,4) f32
    const int*   lens = (const int*)d_in[1];      // (8,)
    float* out = (float*)d_out;

    cudaFuncSetAttribute(fps_kernel,
                         cudaFuncAttributeMaxDynamicSharedMemorySize, FPS_SMEM);

    // fps is launch #4 -> ncu capture verifies the 1024-thread change
    nop_kernel<<<1, 32>>>();
    nop_kernel<<<1, 32>>>();
    nop_kernel<<<1, 32>>>();
    fps_kernel<<<BB, FPS_T, FPS_SMEM>>>(pts, lens, out + OFF_CENTERS);
    ballquery_kernel<<<dim3(64, BB), 256>>>(pts, lens);
    sort_emit_kernel<<<dim3(NG, BB), 256>>>(pts, out + OFF_GROUPS, out + OFF_PMASK);
    emask_kernel<<<BB, CTX>>>(out + OFF_EMASK);
}

// round 13
// speedup vs baseline: 1.3707x; 1.0017x over previous
#include <cuda_runtime.h>
#include <cuda_bf16.h>

// Problem constants
#define BB 8
#define NPTS 16384
#define NG 512          // NUM_GROUPS
#define GS 32           // GROUP_SIZE
#define UK 512          // UPSCALE_K
#define CTX 256         // CONTEXT
#define R2 0.25f        // RADIUS^2

// Output layout (float32, flattened concat of the reference tuple)
#define OFF_GROUPS   0          // 8*256*32*4 = 262144
#define OFF_CENTERS  262144     // 8*256*4   = 8192
#define OFF_EMASK    270336     // 8*256     = 2048
#define OFF_PMASK    272384     // 8*256*32  = 65536

// ---------------- device scratch (no allocations allowed) ----------------
__device__ float4             g_centers[BB * NG];
__device__ unsigned long long g_cand[(size_t)BB * NG * UK];       // 16MB candidate keys
__device__ int                g_cand_cnt[BB * NG];
__device__ int                g_group_len[BB];

// exact (no fma contraction) squared distance, reduce order ((dx^2+dy^2)+dz^2)
__device__ __forceinline__ float d2_exact(float dx, float dy, float dz) {
    return __fadd_rn(__fadd_rn(__fmul_rn(dx, dx), __fmul_rn(dy, dy)), __fmul_rn(dz, dz));
}

__device__ __forceinline__ unsigned encf(float f) {       // order-preserving float->u32
    unsigned u = __float_as_uint(f);
    return (u & 0x80000000u) ? ~u : (u | 0x80000000u);
}
__device__ __forceinline__ unsigned redux_max_u32(unsigned v) {
    unsigned r; asm("redux.sync.max.u32 %0, %1, 0xffffffff;" : "=r"(r) : "r"(v)); return r;
}
__device__ __forceinline__ unsigned redux_min_u32(unsigned v) {
    unsigned r; asm("redux.sync.min.u32 %0, %1, 0xffffffff;" : "=r"(r) : "r"(v)); return r;
}

// packed f32x2 helpers (two independent fp32 RN lanes — bit-exact vs scalar).
// NOTE: only add/mul/fma exist in f32x2 form on sm_103a; min/max stay scalar.
#define PACK2(o, lo, hi)  asm("mov.b64 %0, {%1, %2};" : "=l"(o) : "f"(lo), "f"(hi))
#define UNPACK2(lo, hi, i) asm("mov.b64 {%0, %1}, %2;" : "=f"(lo), "=f"(hi) : "l"(i))
#define ADDX2(o, a, b)    asm("add.rn.f32x2 %0, %1, %2;" : "=l"(o) : "l"(a), "l"(b))
#define MULX2(o, a, b)    asm("mul.rn.f32x2 %0, %1, %2;" : "=l"(o) : "l"(a), "l"(b))

__global__ void nop_kernel() {}

// =====================================================================
// K1: dense FPS, 1024 threads (8 warps/SMSP for latency hiding),
// 8 point-pairs/thread. X,Y packed in registers (32 regs), mind[16],
// z pairs in smem. Same single-barrier iteration and redundant
// 32-key redux reduce; arithmetic bit-identical to the 512-thr version.
// =====================================================================
#define FPS_T 1024
#define PAIRS 8
#define FPS_SMEM (NPTS * 8 + NPTS * 4)   // sxy[NPTS] float2 + z pairs float2[NPTS/2]

__global__ void __launch_bounds__(FPS_T, 1)
fps_kernel(const float4* __restrict__ pts, const int* __restrict__ lengths,
           float* __restrict__ out_centers /* d_out + OFF_CENTERS */) {
    extern __shared__ float smem[];
    float2* __restrict__ sxy = (float2*)smem;              // [NPTS] by point
    float2* __restrict__ szp = (float2*)(smem + 2 * NPTS); // [NPTS/2] z pairs
    __shared__ unsigned long long s_wk[2][32];             // double-buffered warp keys
    __shared__ int s_cidx[NG];

    const int b = blockIdx.x, t = threadIdx.x;
    const int wid = t >> 5, lane = t & 31;
    const float4* __restrict__ P = pts + (size_t)b * NPTS;
    const int len = lengths[b];

    unsigned long long X[PAIRS], Y[PAIRS];
    float mind[2 * PAIRS];

#pragma unroll
    for (int i = 0; i < PAIRS; i++) {
        int q = i * FPS_T + t;
        int p0 = 2 * q, p1 = 2 * q + 1;
        float4 v0 = P[p0], v1 = P[p1];
        bool va = (p0 < len), vb = (p1 < len);
        float x0 = va ? v0.x : 1e18f, y0 = va ? v0.y : 1e18f, z0 = va ? v0.z : 1e18f;
        float x1 = vb ? v1.x : 1e18f, y1 = vb ? v1.y : 1e18f, z1 = vb ? v1.z : 1e18f;
        PACK2(X[i], x0, x1);
        PACK2(Y[i], y0, y1);
        sxy[p0] = make_float2(x0, y0);
        sxy[p1] = make_float2(x1, y1);
        szp[q]  = make_float2(z0, z1);
        mind[2 * i]     = va ? 1e10f : -1e30f;
        mind[2 * i + 1] = vb ? 1e10f : -1e30f;
    }
    float4 v0 = __ldg(&P[0]);
    float wx = v0.x, wy = v0.y, wz = v0.z;
    int wpt = 0;
    if (t == 0) { s_cidx[0] = 0; g_group_len[b] = 0; }
    __syncthreads();

    for (int k = 1; k < NG; k++) {
        unsigned long long nCx, nCy, nCz;
        PACK2(nCx, -wx, -wx);
        PACK2(nCy, -wy, -wy);
        PACK2(nCz, -wz, -wz);

        float fm = -1e30f;
#pragma unroll
        for (int i = 0; i < PAIRS; i++) {
            int q = i * FPS_T + t;
            float2 zz = szp[q];
            unsigned long long Zp, dx, dy, dz, sx, sy, sz, s1, d2p;
            PACK2(Zp, zz.x, zz.y);
            ADDX2(dx, X[i], nCx);           // x - cx  (add of negated, IEEE exact)
            ADDX2(dy, Y[i], nCy);
            ADDX2(dz, Zp,  nCz);
            MULX2(sx, dx, dx);
            MULX2(sy, dy, dy);
            MULX2(sz, dz, dz);
            ADDX2(s1, sx, sy);              // (dx^2 + dy^2)
            ADDX2(d2p, s1, sz);             // ... + dz^2   (same order as scalar)
            float lo, hi;
            UNPACK2(lo, hi, d2p);
            float m0 = fminf(mind[2 * i],     lo);
            float m1 = fminf(mind[2 * i + 1], hi);
            mind[2 * i] = m0; mind[2 * i + 1] = m1;
            fm = fmaxf(fm, fmaxf(m0, m1));
        }

        // warp argmax: max value (redux), min point index among matches
        unsigned ek = encf(fm);
        unsigned wm = redux_max_u32(ek);
        unsigned mybp = 0xFFFFFFFFu;
        if (ek == wm) {                      // predicated rescan (winning lanes only)
#pragma unroll
            for (int i = PAIRS - 1; i >= 0; i--) {
                int q = i * FPS_T + t;
                if (mind[2 * i + 1] == fm) mybp = (unsigned)(2 * q + 1);
                if (mind[2 * i]     == fm) mybp = (unsigned)(2 * q);
            }
        }
        unsigned wi = redux_min_u32(mybp);
        const int par = k & 1;
        if (lane == 0)
            s_wk[par][wid] = ((unsigned long long)wm << 32) | (0xFFFFFFFFu - wi);
        __syncthreads();                     // ONE barrier per iteration

        // every warp redundantly reduces the 32 keys -> identical winner
        unsigned long long kk = s_wk[par][lane];
        unsigned khi = (unsigned)(kk >> 32), klo = (unsigned)kk;
        unsigned mh = redux_max_u32(khi);
        unsigned ml = redux_max_u32((khi == mh) ? klo : 0u);
        wpt = (int)(0xFFFFFFFFu - ml);
        float2 xy = sxy[wpt];
        float2 z2 = szp[wpt >> 1];
        wx = xy.x; wy = xy.y; wz = (wpt & 1) ? z2.y : z2.x;
        if (t == 0) s_cidx[k] = wpt;
    }
    __syncthreads();

    // tail: gather centers (all 4 channels incl. energy)
    if (t < NG) {
        int p = s_cidx[t];
        float4 v = __ldg(&P[p]);
        g_centers[b * NG + t] = v;
        if (t < CTX) ((float4*)out_centers)[b * CTX + t] = v;
    }
}

// =====================================================================
// K2: ball query, warp-per-center, MLP=8. grid (64, 8), 256 threads.
// 8 independent LDG.128 tiles front-batched, then 8 ordered ballot
// rounds — exposed gmem latency /8. Candidate set/order unchanged.
// =====================================================================
__global__ __launch_bounds__(256, 4)
void ballquery_kernel(const float4* __restrict__ pts, const int* __restrict__ lengths) {
    const int b = blockIdx.y;
    const int wid = threadIdx.x >> 5, lane = threadIdx.x & 31;
    const int gi = blockIdx.x * 8 + wid;          // center index 0..511
    const int len = lengths[b];
    const float4* __restrict__ P = pts + (size_t)b * NPTS;
    const unsigned lt = (1u << lane) - 1u;

    float4 cc = g_centers[b * NG + gi];
    const float cx = cc.x, cy = cc.y, cz = cc.z;
    unsigned long long* __restrict__ buf = g_cand + (size_t)(b * NG + gi) * UK;

    int cnt = 0;
    for (int p0 = 0; p0 < NPTS && cnt < UK; p0 += 256) {
        float4 v[8];
#pragma unroll
        for (int j = 0; j < 8; j++)                // 8 independent loads: MLP=8
            v[j] = __ldg(&P[p0 + j * 32 + lane]);
#pragma unroll
        for (int j = 0; j < 8; j++) {              // ordered ballot rounds
            int p = p0 + j * 32 + lane;
            bool pred = (p < len) && (d2_exact(v[j].x - cx, v[j].y - cy, v[j].z - cz) < R2);
            unsigned m = __ballot_sync(0xffffffffu, pred);
            if (m) {
                int rnk = cnt + __popc(m & lt);
                if (pred && rnk < UK) {
                    unsigned eb = __float_as_uint(v[j].w);
                    unsigned ekey = (eb & 0x80000000u) ? ~eb : (eb | 0x80000000u);
                    buf[rnk] = ((unsigned long long)ekey << 32)
                             | (unsigned)(0xFFFFFFFFu - (unsigned)p);
                }
                cnt += __popc(m);
                if (cnt >= UK) { cnt = UK; break; }
            }
        }
    }
    if (lane == 0) g_cand_cnt[b * NG + gi] = cnt;
}

// =====================================================================
// K3: per-group adaptive bitonic (M = next pow2 >= cnt, min 32) descending
// sort of candidate keys, then emit. grid (512, 8), 256 threads.
// =====================================================================
__global__ __launch_bounds__(256, 8)
void sort_emit_kernel(const float4* __restrict__ pts,
                      float* __restrict__ out_groups /* d_out */,
                      float* __restrict__ out_pmask  /* d_out + OFF_PMASK */) {
    const int gi = blockIdx.x;
    const int b  = blockIdx.y;
    const int g  = b * NG + gi;
    const int t  = threadIdx.x;

    __shared__ unsigned long long s[UK];
    const int cnt = g_cand_cnt[g];
    const unsigned long long* __restrict__ src = g_cand + (size_t)g * UK;

    int M = GS;
    while (M < cnt) M <<= 1;                       // 32..512, CTA-uniform

    for (int i = t; i < M; i += 256)
        s[i] = (i < cnt) ? src[i] : 0ull;

    for (int kk = 2; kk <= M; kk <<= 1) {
        for (int j = kk >> 1; j > 0; j >>= 1) {
            __syncthreads();
            for (int e = t; e < M; e += 256) {
                int l = e ^ j;
                if (l > e) {
                    unsigned long long a = s[e], c = s[l];
                    bool dsc = ((e & kk) == 0);
                    bool sw = dsc ? (a < c) : (a > c);
                    if (sw) { s[e] = c; s[l] = a; }
                }
            }
        }
    }
    __syncthreads();

    const int pl = min(cnt, GS);
    if (t == 0 && cnt >= GS) atomicAdd(&g_group_len[b], 1);

    if (gi < CTX) {
        if (t < GS * 4) {
            int slot = t >> 2, ch = t & 3;
            int ss = (slot < pl) ? slot : 0;
            unsigned p = 0xFFFFFFFFu - (unsigned)(s[ss] & 0xFFFFFFFFull);
            const float* pp = (const float*)(pts + ((size_t)b * NPTS + p));
            out_groups[(((size_t)(b * CTX + gi)) * GS + slot) * 4 + ch] = pp[ch];
        } else if (t < GS * 4 + GS) {
            int slot = t - GS * 4;
            out_pmask[(size_t)(b * CTX + gi) * GS + slot] = (slot < pl) ? 1.0f : 0.0f;
        }
    }
}

// =====================================================================
// K4: embedding mask
// =====================================================================
__global__ void emask_kernel(float* __restrict__ em) {
    int b = blockIdx.x, t = threadIdx.x;
    em[b * CTX + t] = (t < g_group_len[b]) ? 1.0f : 0.0f;
}

// =====================================================================
extern "C" void kernel_launch(void* const* d_in, const int* in_sizes, int n_in,
                              void* d_out, int out_size) {
    const float4* pts = (const float4*)d_in[0];   // (8,16384,4) f32
    const int*   lens = (const int*)d_in[1];      // (8,)
    float* out = (float*)d_out;

    cudaFuncSetAttribute(fps_kernel,
                         cudaFuncAttributeMaxDynamicSharedMemorySize, FPS_SMEM);

    // fps is launch #4 -> ncu capture verifies the 1024-thread change
    nop_kernel<<<1, 32>>>();
    nop_kernel<<<1, 32>>>();
    nop_kernel<<<1, 32>>>();
    fps_kernel<<<BB, FPS_T, FPS_SMEM>>>(pts, lens, out + OFF_CENTERS);
    ballquery_kernel<<<dim3(64, BB), 256>>>(pts, lens);
    sort_emit_kernel<<<dim3(NG, BB), 256>>>(pts, out + OFF_GROUPS, out + OFF_PMASK);
    emask_kernel<<<BB, CTX>>>(out + OFF_EMASK);
}